// round 1
// baseline (speedup 1.0000x reference)
#include <cuda_runtime.h>

#define NN 32
#define MM 8
#define PP 16
#define BB 64
#define TT 128
#define NP1 33

// ---------------- global scratch (no cudaMalloc allowed) ----------------
__device__ float g_muf[BB][TT][NN];
__device__ float g_mup[BB][TT][NN];
__device__ float g_Sigf[BB][TT][NN][NN];
__device__ float g_Sigp[BB][TT][NN][NN];
__device__ float g_J[BB][TT][NN][NN];   // valid for t in [0, TT-2]

// ---------------- forward Kalman filter: 1 CTA per batch ----------------
__global__ void __launch_bounds__(1024) fwd_kernel(
    const float* __restrict__ Y, const float* __restrict__ U,
    const float* __restrict__ A, const float* __restrict__ Bm,
    const float* __restrict__ C, const float* __restrict__ mu0,
    const float* __restrict__ Sigma0)
{
    const int b = blockIdx.x;
    const int j = threadIdx.x;   // column
    const int i = threadIdx.y;   // row
    const int tid = i * 32 + j;

    __shared__ float sA[NN][NN + 1];
    __shared__ float sB[NN][MM + 1];
    __shared__ float sC[PP][NN + 1];
    __shared__ float sSig[NN][NN + 1];
    __shared__ float sTmp[NN][NN + 1];
    __shared__ float sSigp[NN][NN + 1];
    __shared__ float sCS[PP][NN + 1];
    __shared__ float sAug[PP][PP + NN + 1];   // [S | C*Sigp]  16 x 48
    __shared__ float sK[NN][PP + 1];
    __shared__ float sIKC[NN][NN + 1];
    __shared__ float sE[NN][NN + 1];
    __shared__ float smu[NN], smup[NN], sr[PP], su[MM], sy[PP];

    // init carry
    sSig[i][j] = Sigma0[i * NN + j];
    if (tid < NN) smu[tid] = mu0[tid];
    __syncthreads();

    for (int t = 0; t < TT; ++t) {
        const size_t bt = (size_t)b * TT + t;
        const float* Abt = A  + bt * (NN * NN);
        const float* Bbt = Bm + bt * (NN * MM);
        const float* Cbt = C  + bt * (PP * NN);
        const float* Ybt = Y  + bt * PP;
        const float* Ubt = U  + bt * MM;

        // -------- load step inputs --------
        sA[i][j] = Abt[i * NN + j];
        if (i < PP) sC[i][j] = Cbt[i * NN + j];
        if (j < MM) sB[i][j] = Bbt[i * MM + j];
        if (i == 31 && j < PP) sy[j] = Ybt[j];
        if (i == 30 && j < MM) su[j] = Ubt[j];
        __syncthreads();

        // -------- phase 1: tmp = A @ Sig ; mu_p = A mu + B u --------
        {
            float acc = 0.f;
            #pragma unroll
            for (int k = 0; k < NN; ++k) acc += sA[i][k] * sSig[k][j];
            sTmp[i][j] = acc;
        }
        if (i == 0) {
            float m = 0.f;
            #pragma unroll
            for (int k = 0; k < NN; ++k) m += sA[j][k] * smu[k];
            #pragma unroll
            for (int k = 0; k < MM; ++k) m += sB[j][k] * su[k];
            smup[j] = m;
        }
        __syncthreads();

        // -------- phase 2: Sigp = tmp @ A^T + Q ; r = y - C mu_p --------
        {
            float acc = 0.f;
            #pragma unroll
            for (int k = 0; k < NN; ++k) acc += sTmp[i][k] * sA[j][k];
            sSigp[i][j] = acc + ((i == j) ? 0.01f : 0.f);
        }
        if (i == 1 && j < PP) {
            float m = 0.f;
            #pragma unroll
            for (int k = 0; k < NN; ++k) m += sC[j][k] * smup[k];
            sr[j] = sy[j] - m;
        }
        __syncthreads();

        // -------- phase 3: CS = C @ Sigp --------
        if (i < PP) {
            float acc = 0.f;
            #pragma unroll
            for (int k = 0; k < NN; ++k) acc += sC[i][k] * sSigp[k][j];
            sCS[i][j] = acc;
        }
        __syncthreads();

        // -------- phase 4: Aug = [ sym(CS C^T + R) | CS ] --------
        if (i < PP) {
            if (j < PP) {
                float a1 = 0.f, a2 = 0.f;
                #pragma unroll
                for (int k = 0; k < NN; ++k) {
                    a1 += sCS[i][k] * sC[j][k];
                    a2 += sCS[j][k] * sC[i][k];
                }
                sAug[i][j] = 0.5f * (a1 + a2) + ((i == j) ? 0.01f : 0.f);
            }
            sAug[i][PP + j] = sCS[i][j];   // cols 16..47
        }
        __syncthreads();

        // -------- phase 5: Gauss-Jordan (S is SPD, no pivoting) --------
        // thread covers column j (0..31) and column 32+j (if j<16) -> 0..47
        for (int k = 0; k < PP; ++k) {
            const float piv = sAug[k][k];
            const float pr = 1.0f / piv;
            float aik = 0.f, r0 = 0.f, r1 = 0.f, m0 = 0.f, m1 = 0.f;
            if (i < PP) {
                aik = sAug[i][k];
                r0 = sAug[k][j];
                m0 = sAug[i][j];
                if (j < PP) { r1 = sAug[k][NN + j]; m1 = sAug[i][NN + j]; }
            }
            __syncthreads();
            if (i < PP) {
                if (i == k) {
                    sAug[k][j] = r0 * pr;
                    if (j < PP) sAug[k][NN + j] = r1 * pr;
                } else {
                    const float f = aik * pr;
                    sAug[i][j] = m0 - f * r0;
                    if (j < PP) sAug[i][NN + j] = m1 - f * r1;
                }
            }
            __syncthreads();
        }

        // -------- phase 6: K = (S^{-1} CS)^T ; IKC = I - K C ; mu_f --------
        if (i < PP) sK[j][i] = sAug[i][PP + j];
        __syncthreads();
        {
            float acc = (i == j) ? 1.0f : 0.0f;
            #pragma unroll
            for (int k = 0; k < PP; ++k) acc -= sK[i][k] * sC[k][j];
            sIKC[i][j] = acc;
        }
        if (i == 0) {
            float m = smup[j];
            #pragma unroll
            for (int k = 0; k < PP; ++k) m += sK[j][k] * sr[k];
            smu[j] = m;  // mu_f
        }
        __syncthreads();

        // -------- phase 7: tmp = IKC @ Sigp --------
        {
            float acc = 0.f;
            #pragma unroll
            for (int k = 0; k < NN; ++k) acc += sIKC[i][k] * sSigp[k][j];
            sTmp[i][j] = acc;
        }
        __syncthreads();

        // -------- phase 8: E = tmp @ IKC^T + 0.01 * K K^T --------
        {
            float acc = 0.f;
            #pragma unroll
            for (int k = 0; k < NN; ++k) acc += sTmp[i][k] * sIKC[j][k];
            float kk = 0.f;
            #pragma unroll
            for (int k = 0; k < PP; ++k) kk += sK[i][k] * sK[j][k];
            sE[i][j] = acc + 0.01f * kk;
        }
        __syncthreads();

        // -------- phase 9: Sig_f = sym(E); stash step results --------
        {
            const float v = 0.5f * (sE[i][j] + sE[j][i]);
            sSig[i][j] = v;
            g_Sigf[b][t][i][j] = v;
            g_Sigp[b][t][i][j] = sSigp[i][j];
            if (i == 0) { g_muf[b][t][j] = smu[j]; g_mup[b][t][j] = smup[j]; }
        }
        __syncthreads();
    }
}

// -------- smoother gains J_t = Sigf_t A_t^T Sigp_{t+1}^{-1}: fully parallel --------
__global__ void __launch_bounds__(1024) jgain_kernel(const float* __restrict__ A)
{
    const int t = blockIdx.x;     // 0..TT-2
    const int b = blockIdx.y;
    const int j = threadIdx.x;
    const int i = threadIdx.y;

    __shared__ float sSf[NN][NN + 1];
    __shared__ float sA[NN][NN + 1];
    __shared__ float sX[NN][NN + 1];
    __shared__ float sAug[NN][2 * NN + 1];   // [Sigp_{t+1} | X^T]  32 x 64

    sSf[i][j]  = g_Sigf[b][t][i][j];
    sA[i][j]   = A[(((size_t)b * TT) + t) * NN * NN + i * NN + j];
    sAug[i][j] = g_Sigp[b][t + 1][i][j];
    __syncthreads();

    // X = Sigf @ A^T
    {
        float acc = 0.f;
        #pragma unroll
        for (int k = 0; k < NN; ++k) acc += sSf[i][k] * sA[j][k];
        sX[i][j] = acc;
    }
    __syncthreads();
    sAug[i][NN + j] = sX[j][i];   // RHS = X^T
    __syncthreads();

    // Gauss-Jordan: Sigp_{t+1} is SPD. thread covers cols j and NN+j.
    for (int k = 0; k < NN; ++k) {
        const float piv = sAug[k][k];
        const float pr = 1.0f / piv;
        const float aik = sAug[i][k];
        const float r0 = sAug[k][j],      r1 = sAug[k][NN + j];
        const float m0 = sAug[i][j],      m1 = sAug[i][NN + j];
        __syncthreads();
        if (i == k) {
            sAug[k][j] = r0 * pr;  sAug[k][NN + j] = r1 * pr;
        } else {
            const float f = aik * pr;
            sAug[i][j] = m0 - f * r0;
            sAug[i][NN + j] = m1 - f * r1;
        }
        __syncthreads();
    }

    // J = Z^T where Z = Sigp^{-1} X^T
    g_J[b][t][i][j] = sAug[j][NN + i];
}

// -------- backward RTS recursion: 1 CTA per batch, J precomputed --------
__global__ void __launch_bounds__(1024) bwd_kernel(float* __restrict__ out)
{
    const int b = blockIdx.x;
    const int j = threadIdx.x;
    const int i = threadIdx.y;

    __shared__ float sSig[NN][NN + 1];   // Sig_s carry
    __shared__ float sJ[NN][NN + 1];
    __shared__ float sD[NN][NN + 1];
    __shared__ float sTmp[NN][NN + 1];
    __shared__ float sE[NN][NN + 1];
    __shared__ float smu[NN], sdm[NN];

    // t = T-1: smoothed == filtered
    sSig[i][j] = g_Sigf[b][TT - 1][i][j];
    if (i == 0) smu[j] = g_muf[b][TT - 1][j];
    __syncthreads();
    {
        const size_t base = (((size_t)b * TT + (TT - 1)) * NN + i) * NP1;
        out[base + 1 + j] = sSig[i][j];
        if (j == 0) out[base] = smu[i];
    }

    for (int t = TT - 2; t >= 0; --t) {
        sJ[i][j] = g_J[b][t][i][j];
        sD[i][j] = sSig[i][j] - g_Sigp[b][t + 1][i][j];
        if (i == 0) sdm[j] = smu[j] - g_mup[b][t + 1][j];
        __syncthreads();

        // tmp = J @ (Sig_s - Sigp_{t+1})
        {
            float acc = 0.f;
            #pragma unroll
            for (int k = 0; k < NN; ++k) acc += sJ[i][k] * sD[k][j];
            sTmp[i][j] = acc;
        }
        __syncthreads();

        // E = Sigf + tmp @ J^T ; mu_n = mu_f + J (mu_s - mu_p1)
        {
            float acc = g_Sigf[b][t][i][j];
            #pragma unroll
            for (int k = 0; k < NN; ++k) acc += sTmp[i][k] * sJ[j][k];
            sE[i][j] = acc;
        }
        if (i == 0) {
            float m = g_muf[b][t][j];
            #pragma unroll
            for (int k = 0; k < NN; ++k) m += sJ[j][k] * sdm[k];
            smu[j] = m;
        }
        __syncthreads();

        // Sig_s = sym(E); emit
        {
            const float v = 0.5f * (sE[i][j] + sE[j][i]);
            sSig[i][j] = v;
            const size_t base = (((size_t)b * TT + t) * NN + i) * NP1;
            out[base + 1 + j] = v;
            if (j == 0) out[base] = smu[i];
        }
        __syncthreads();
    }
}

// ---------------- launch ----------------
extern "C" void kernel_launch(void* const* d_in, const int* in_sizes, int n_in,
                              void* d_out, int out_size)
{
    const float* Y      = (const float*)d_in[0];
    const float* U      = (const float*)d_in[1];
    const float* A      = (const float*)d_in[2];
    const float* Bm     = (const float*)d_in[3];
    const float* C      = (const float*)d_in[4];
    const float* mu0    = (const float*)d_in[5];
    const float* Sigma0 = (const float*)d_in[6];
    float* out = (float*)d_out;

    dim3 blk(32, 32);
    fwd_kernel<<<BB, blk>>>(Y, U, A, Bm, C, mu0, Sigma0);
    jgain_kernel<<<dim3(TT - 1, BB), blk>>>(A);
    bwd_kernel<<<BB, blk>>>(out);
}

// round 2
// speedup vs baseline: 1.4057x; 1.4057x over previous
#include <cuda_runtime.h>

#define NN 32
#define MM 8
#define PP 16
#define BB 64
#define TT 128
#define NP1 33

// ---------------- global scratch (no cudaMalloc allowed) ----------------
__device__ float g_muf[BB][TT][NN];
__device__ float g_mup[BB][TT][NN];
__device__ float g_Sigf[BB][TT][NN][NN];
__device__ float g_Sigp[BB][TT][NN][NN];
__device__ float g_J[BB][TT][NN][NN];   // valid for t in [0, TT-2]

// ================= forward filter: 1 CTA / batch, 256 threads =================
__global__ void __launch_bounds__(256) fwd_kernel(
    const float* __restrict__ Y, const float* __restrict__ U,
    const float* __restrict__ A, const float* __restrict__ Bm,
    const float* __restrict__ C, const float* __restrict__ mu0,
    const float* __restrict__ Sigma0)
{
    const int b = blockIdx.x;
    const int tid = threadIdx.x;
    const int tx = tid & 15, ty = tid >> 4;     // 16x16 thread grid, 2x2 tiles
    const int lane = tid & 31, wid = tid >> 5;

    __shared__ float sA[NN][NN + 1], sC[PP][NN + 1], sB[NN][MM + 1];
    __shared__ float sSig[NN][NN + 1], sTmp[NN][NN + 1], sSigp[NN][NN + 1];
    __shared__ float sH[PP][NN + 1], sCS[PP][NN + 1], sS0[PP][PP + 1], sK[NN][PP + 1];
    __shared__ float smu[NN], smup[NN], sr[PP], sy[PP], su[MM];

    const float* Ab = A  + (size_t)b * TT * NN * NN;
    const float* Cb = C  + (size_t)b * TT * PP * NN;
    const float* Bb = Bm + (size_t)b * TT * NN * MM;
    const float* Yb = Y  + (size_t)b * TT * PP;
    const float* Ub = U  + (size_t)b * TT * MM;

    // init carry + t=0 inputs
    for (int idx = tid; idx < NN * NN; idx += 256) sSig[idx >> 5][idx & 31] = Sigma0[idx];
    if (tid < NN) smu[tid] = mu0[tid];
    for (int idx = tid; idx < NN * NN; idx += 256) sA[idx >> 5][idx & 31] = Ab[idx];
    for (int idx = tid; idx < PP * NN; idx += 256) sC[idx >> 5][idx & 31] = Cb[idx];
    if (tid < NN * MM) sB[tid >> 3][tid & 7] = Bb[tid];
    if (tid < PP) sy[tid] = Yb[tid];
    else if (tid < PP + MM) su[tid - PP] = Ub[tid - PP];
    __syncthreads();

    for (int t = 0; t < TT; ++t) {
        // ---- P1: tmp = A @ Sig ; mu_p = A mu + B u ----
        {
            float a00 = 0.f, a01 = 0.f, a10 = 0.f, a11 = 0.f;
            #pragma unroll
            for (int k = 0; k < NN; ++k) {
                const float l0 = sA[ty][k],   l1 = sA[ty + 16][k];
                const float r0 = sSig[k][tx], r1 = sSig[k][tx + 16];
                a00 += l0 * r0; a01 += l0 * r1; a10 += l1 * r0; a11 += l1 * r1;
            }
            sTmp[ty][tx] = a00;      sTmp[ty][tx + 16] = a01;
            sTmp[ty + 16][tx] = a10; sTmp[ty + 16][tx + 16] = a11;
        }
        if (tid < NN) {
            float m = 0.f;
            #pragma unroll
            for (int k = 0; k < NN; ++k) m += sA[tid][k] * smu[k];
            #pragma unroll
            for (int k = 0; k < MM; ++k) m += sB[tid][k] * su[k];
            smup[tid] = m;
        }
        __syncthreads();

        // ---- P2: Sigp = tmp@A^T + Q ; H = C@tmp ; r = y - C mu_p ----
        {
            float a00 = 0.f, a01 = 0.f, a10 = 0.f, a11 = 0.f;
            #pragma unroll
            for (int k = 0; k < NN; ++k) {
                const float l0 = sTmp[ty][k],  l1 = sTmp[ty + 16][k];
                const float r0 = sA[tx][k],    r1 = sA[tx + 16][k];
                a00 += l0 * r0; a01 += l0 * r1; a10 += l1 * r0; a11 += l1 * r1;
            }
            const float q = (ty == tx) ? 0.01f : 0.f;
            a00 += q; a11 += q;
            sSigp[ty][tx] = a00;      sSigp[ty][tx + 16] = a01;
            sSigp[ty + 16][tx] = a10; sSigp[ty + 16][tx + 16] = a11;
            float* gp = &g_Sigp[b][t][0][0];
            gp[ty * NN + tx] = a00;             gp[ty * NN + tx + 16] = a01;
            gp[(ty + 16) * NN + tx] = a10;      gp[(ty + 16) * NN + tx + 16] = a11;
        }
        {
            float h0 = 0.f, h1 = 0.f;
            #pragma unroll
            for (int k = 0; k < NN; ++k) {
                const float c0 = sC[ty][k];
                h0 += c0 * sTmp[k][tx]; h1 += c0 * sTmp[k][tx + 16];
            }
            sH[ty][tx] = h0; sH[ty][tx + 16] = h1;
        }
        if (tid < PP) {
            float m = 0.f;
            #pragma unroll
            for (int k = 0; k < NN; ++k) m += sC[tid][k] * smup[k];
            sr[tid] = sy[tid] - m;
        }
        __syncthreads();

        // ---- P3: CS = H@A^T + 0.01*C  (= C @ Sigp) ----
        {
            float a0 = 0.f, a1 = 0.f;
            #pragma unroll
            for (int k = 0; k < NN; ++k) {
                const float h = sH[ty][k];
                a0 += h * sA[tx][k]; a1 += h * sA[tx + 16][k];
            }
            sCS[ty][tx]      = a0 + 0.01f * sC[ty][tx];
            sCS[ty][tx + 16] = a1 + 0.01f * sC[ty][tx + 16];
        }
        __syncthreads();

        // ---- P4: S0 = CS @ C^T ----
        {
            float a0 = 0.f;
            #pragma unroll
            for (int k = 0; k < NN; ++k) a0 += sCS[ty][k] * sC[tx][k];
            sS0[ty][tx] = a0;
        }
        __syncthreads();

        // ---- P5: warp0 register Gauss-Jordan on [sym(S0)+R | CS] ;
        //          warps 1..7 stash next step's inputs ----
        if (wid == 0) {
            float colA[PP], colB[PP];
            #pragma unroll
            for (int i = 0; i < PP; ++i) {
                colA[i] = (lane < PP)
                    ? 0.5f * (sS0[i][lane] + sS0[lane][i]) + ((i == lane) ? 0.01f : 0.f)
                    : sCS[i][lane - PP];
                colB[i] = (lane < PP) ? sCS[i][PP + lane] : 0.f;
            }
            #pragma unroll
            for (int k = 0; k < PP; ++k) {
                float f[PP];
                #pragma unroll
                for (int i = 0; i < PP; ++i) f[i] = __shfl_sync(0xffffffffu, colA[i], k);
                const float pr = 1.0f / f[k];
                #pragma unroll
                for (int i = 0; i < PP; ++i) {
                    if (i != k) {
                        const float g = f[i] * pr;
                        colA[i] -= g * colA[k];
                        colB[i] -= g * colB[k];
                    }
                }
                colA[k] *= pr; colB[k] *= pr;
            }
            // K[j][i] = Sol[i][j]; Sol cols 0..15 live in lanes 16..31 (colA),
            // Sol cols 16..31 live in lanes 0..15 (colB)
            if (lane >= PP) {
                #pragma unroll
                for (int i = 0; i < PP; ++i) sK[lane - PP][i] = colA[i];
            } else {
                #pragma unroll
                for (int i = 0; i < PP; ++i) sK[PP + lane][i] = colB[i];
            }
        } else if (t + 1 < TT) {
            const int wt = tid - 32;
            const float* An = Ab + (size_t)(t + 1) * NN * NN;
            const float* Cn = Cb + (size_t)(t + 1) * PP * NN;
            const float* Bn = Bb + (size_t)(t + 1) * NN * MM;
            for (int idx = wt; idx < NN * NN; idx += 224) sA[idx >> 5][idx & 31] = An[idx];
            for (int idx = wt; idx < PP * NN; idx += 224) sC[idx >> 5][idx & 31] = Cn[idx];
            for (int idx = wt; idx < NN * MM; idx += 224) sB[idx >> 3][idx & 7] = Bn[idx];
            if (wt < PP) sy[wt] = Yb[(t + 1) * PP + wt];
            else if (wt < PP + MM) su[wt - PP] = Ub[(t + 1) * MM + (wt - PP)];
        }
        __syncthreads();

        // ---- P6: X = Sigp - K @ CS ; mu_f = mu_p + K r ----
        {
            float a00 = 0.f, a01 = 0.f, a10 = 0.f, a11 = 0.f;
            #pragma unroll
            for (int k = 0; k < PP; ++k) {
                const float k0 = sK[ty][k],  k1 = sK[ty + 16][k];
                const float c0 = sCS[k][tx], c1 = sCS[k][tx + 16];
                a00 += k0 * c0; a01 += k0 * c1; a10 += k1 * c0; a11 += k1 * c1;
            }
            sTmp[ty][tx]          = sSigp[ty][tx]          - a00;
            sTmp[ty][tx + 16]     = sSigp[ty][tx + 16]     - a01;
            sTmp[ty + 16][tx]     = sSigp[ty + 16][tx]     - a10;
            sTmp[ty + 16][tx + 16] = sSigp[ty + 16][tx + 16] - a11;
        }
        if (tid < NN) {
            float m = smup[tid];
            #pragma unroll
            for (int k = 0; k < PP; ++k) m += sK[tid][k] * sr[k];
            smu[tid] = m;
            g_muf[b][t][tid] = m;
            g_mup[b][t][tid] = smup[tid];
        }
        __syncthreads();

        // ---- P7: Sig_f = sym(X); carry + stash ----
        {
            const float v00 = 0.5f * (sTmp[ty][tx]           + sTmp[tx][ty]);
            const float v01 = 0.5f * (sTmp[ty][tx + 16]      + sTmp[tx + 16][ty]);
            const float v10 = 0.5f * (sTmp[ty + 16][tx]      + sTmp[tx][ty + 16]);
            const float v11 = 0.5f * (sTmp[ty + 16][tx + 16] + sTmp[tx + 16][ty + 16]);
            sSig[ty][tx] = v00;      sSig[ty][tx + 16] = v01;
            sSig[ty + 16][tx] = v10; sSig[ty + 16][tx + 16] = v11;
            float* gf = &g_Sigf[b][t][0][0];
            gf[ty * NN + tx] = v00;        gf[ty * NN + tx + 16] = v01;
            gf[(ty + 16) * NN + tx] = v10; gf[(ty + 16) * NN + tx + 16] = v11;
        }
        __syncthreads();
    }
}

// ========== smoother gains J_t = Sigf_t A_t^T Sigp_{t+1}^{-1} (parallel) ==========
__global__ void __launch_bounds__(256) jgain_kernel(const float* __restrict__ A)
{
    const int t = blockIdx.x;     // 0..TT-2
    const int b = blockIdx.y;
    const int tid = threadIdx.x;
    const int tx = tid & 15, ty = tid >> 4;

    __shared__ float sSf[NN][NN + 1], sA[NN][NN + 1], sX[NN][NN + 1];
    __shared__ float prow[2][2 * NN];
    __shared__ float sf[2][NN];

    const float* Ab = A + ((size_t)b * TT + t) * NN * NN;
    for (int idx = tid; idx < NN * NN; idx += 256) {
        sSf[idx >> 5][idx & 31] = g_Sigf[b][t][idx >> 5][idx & 31];
        sA[idx >> 5][idx & 31]  = Ab[idx];
    }
    __syncthreads();

    // X = Sigf @ A^T
    {
        float a00 = 0.f, a01 = 0.f, a10 = 0.f, a11 = 0.f;
        #pragma unroll
        for (int k = 0; k < NN; ++k) {
            const float l0 = sSf[ty][k], l1 = sSf[ty + 16][k];
            const float r0 = sA[tx][k],  r1 = sA[tx + 16][k];
            a00 += l0 * r0; a01 += l0 * r1; a10 += l1 * r0; a11 += l1 * r1;
        }
        sX[ty][tx] = a00;      sX[ty][tx + 16] = a01;
        sX[ty + 16][tx] = a10; sX[ty + 16][tx + 16] = a11;
    }
    __syncthreads();

    // Gauss-Jordan on [Sigp_{t+1} | X^T]; each thread owns 8 cols of one row in regs
    const int row = tid >> 3;
    const int c0  = (tid & 7) * 8;
    float r8[8];
    if (c0 < NN) {
        #pragma unroll
        for (int m = 0; m < 8; ++m) r8[m] = g_Sigp[b][t + 1][row][c0 + m];
    } else {
        #pragma unroll
        for (int m = 0; m < 8; ++m) r8[m] = sX[c0 - NN + m][row];   // X^T
    }
    #pragma unroll
    for (int k = 0; k < NN; ++k) {
        const int pb = k & 1;
        if (row == k) {
            #pragma unroll
            for (int m = 0; m < 8; ++m) prow[pb][c0 + m] = r8[m];
        }
        if ((tid & 7) == (k >> 3)) sf[pb][row] = r8[k & 7];
        __syncthreads();
        const float pr = 1.0f / prow[pb][k];
        if (row == k) {
            #pragma unroll
            for (int m = 0; m < 8; ++m) r8[m] *= pr;
        } else {
            const float g = sf[pb][row] * pr;
            #pragma unroll
            for (int m = 0; m < 8; ++m) r8[m] -= g * prow[pb][c0 + m];
        }
    }
    // Z = Sigp^{-1} X^T ; J = Z^T : stage through sX, then coalesced store
    if (c0 >= NN) {
        #pragma unroll
        for (int m = 0; m < 8; ++m) sX[c0 - NN + m][row] = r8[m];
    }
    __syncthreads();
    for (int idx = tid; idx < NN * NN; idx += 256)
        g_J[b][t][idx >> 5][idx & 31] = sX[idx >> 5][idx & 31];
}

// ========== backward RTS recursion: 1 CTA / batch, 256 threads ==========
__global__ void __launch_bounds__(256) bwd_kernel(float* __restrict__ out)
{
    const int b = blockIdx.x;
    const int tid = threadIdx.x;
    const int tx = tid & 15, ty = tid >> 4;

    __shared__ float sJ[NN][NN + 1], sD[NN][NN + 1], sTmp[NN][NN + 1];
    __shared__ float sSig[NN][NN + 1], sSf[NN][NN + 1], sE[NN][NN + 1];
    __shared__ float smu[NN], sdm[NN];

    // t = TT-1: smoothed == filtered
    for (int idx = tid; idx < NN * NN; idx += 256)
        sSig[idx >> 5][idx & 31] = g_Sigf[b][TT - 1][idx >> 5][idx & 31];
    if (tid < NN) smu[tid] = g_muf[b][TT - 1][tid];
    __syncthreads();
    #pragma unroll
    for (int m = 0; m < 4; ++m) {
        const int f = tid + 256 * m; const int i = f >> 5, j = f & 31;
        out[(((size_t)b * TT + (TT - 1)) * NN + i) * NP1 + 1 + j] = sSig[i][j];
    }
    if (tid < NN) out[(((size_t)b * TT + (TT - 1)) * NN + tid) * NP1] = smu[tid];

    // prefetch t = TT-2
    float pJ[4], pSp[4], pSf[4];
    #pragma unroll
    for (int m = 0; m < 4; ++m) {
        const int f = tid + 256 * m; const int i = f >> 5, j = f & 31;
        pJ[m]  = g_J[b][TT - 2][i][j];
        pSp[m] = g_Sigp[b][TT - 1][i][j];
        pSf[m] = g_Sigf[b][TT - 2][i][j];
    }

    for (int t = TT - 2; t >= 0; --t) {
        // stash prefetched tiles; D = Sig_s - Sigp_{t+1}
        #pragma unroll
        for (int m = 0; m < 4; ++m) {
            const int f = tid + 256 * m; const int i = f >> 5, j = f & 31;
            sJ[i][j]  = pJ[m];
            sD[i][j]  = sSig[i][j] - pSp[m];
            sSf[i][j] = pSf[m];
        }
        if (tid < NN) sdm[tid] = smu[tid] - g_mup[b][t + 1][tid];
        __syncthreads();

        // prefetch t-1 while computing
        if (t > 0) {
            #pragma unroll
            for (int m = 0; m < 4; ++m) {
                const int f = tid + 256 * m; const int i = f >> 5, j = f & 31;
                pJ[m]  = g_J[b][t - 1][i][j];
                pSp[m] = g_Sigp[b][t][i][j];
                pSf[m] = g_Sigf[b][t - 1][i][j];
            }
        }

        // tmp = J @ D ; mu_n = mu_f + J dm
        {
            float a00 = 0.f, a01 = 0.f, a10 = 0.f, a11 = 0.f;
            #pragma unroll
            for (int k = 0; k < NN; ++k) {
                const float l0 = sJ[ty][k], l1 = sJ[ty + 16][k];
                const float r0 = sD[k][tx], r1 = sD[k][tx + 16];
                a00 += l0 * r0; a01 += l0 * r1; a10 += l1 * r0; a11 += l1 * r1;
            }
            sTmp[ty][tx] = a00;      sTmp[ty][tx + 16] = a01;
            sTmp[ty + 16][tx] = a10; sTmp[ty + 16][tx + 16] = a11;
        }
        if (tid < NN) {
            float m2 = g_muf[b][t][tid];
            #pragma unroll
            for (int k = 0; k < NN; ++k) m2 += sJ[tid][k] * sdm[k];
            smu[tid] = m2;
        }
        __syncthreads();

        // E = Sigf + tmp @ J^T
        {
            float a00 = sSf[ty][tx],      a01 = sSf[ty][tx + 16];
            float a10 = sSf[ty + 16][tx], a11 = sSf[ty + 16][tx + 16];
            #pragma unroll
            for (int k = 0; k < NN; ++k) {
                const float l0 = sTmp[ty][k], l1 = sTmp[ty + 16][k];
                const float r0 = sJ[tx][k],   r1 = sJ[tx + 16][k];
                a00 += l0 * r0; a01 += l0 * r1; a10 += l1 * r0; a11 += l1 * r1;
            }
            sE[ty][tx] = a00;      sE[ty][tx + 16] = a01;
            sE[ty + 16][tx] = a10; sE[ty + 16][tx + 16] = a11;
        }
        __syncthreads();

        // Sig_s = sym(E); emit; carry
        {
            const float v00 = 0.5f * (sE[ty][tx]           + sE[tx][ty]);
            const float v01 = 0.5f * (sE[ty][tx + 16]      + sE[tx + 16][ty]);
            const float v10 = 0.5f * (sE[ty + 16][tx]      + sE[tx][ty + 16]);
            const float v11 = 0.5f * (sE[ty + 16][tx + 16] + sE[tx + 16][ty + 16]);
            sSig[ty][tx] = v00;      sSig[ty][tx + 16] = v01;
            sSig[ty + 16][tx] = v10; sSig[ty + 16][tx + 16] = v11;
            const size_t base = ((size_t)b * TT + t) * NN;
            out[(base + ty) * NP1 + 1 + tx]           = v00;
            out[(base + ty) * NP1 + 1 + tx + 16]      = v01;
            out[(base + ty + 16) * NP1 + 1 + tx]      = v10;
            out[(base + ty + 16) * NP1 + 1 + tx + 16] = v11;
            if (tid < NN) out[(base + tid) * NP1] = smu[tid];
        }
        __syncthreads();
    }
}

// ---------------- launch ----------------
extern "C" void kernel_launch(void* const* d_in, const int* in_sizes, int n_in,
                              void* d_out, int out_size)
{
    const float* Y      = (const float*)d_in[0];
    const float* U      = (const float*)d_in[1];
    const float* A      = (const float*)d_in[2];
    const float* Bm     = (const float*)d_in[3];
    const float* C      = (const float*)d_in[4];
    const float* mu0    = (const float*)d_in[5];
    const float* Sigma0 = (const float*)d_in[6];
    float* out = (float*)d_out;

    fwd_kernel<<<BB, 256>>>(Y, U, A, Bm, C, mu0, Sigma0);
    jgain_kernel<<<dim3(TT - 1, BB), 256>>>(A);
    bwd_kernel<<<BB, 256>>>(out);
}